// round 9
// baseline (speedup 1.0000x reference)
#include <cuda_runtime.h>
#include <cuda_fp16.h>
#include <cstdint>

#define BB 8
#define LL 2048
#define VV 8192
#define CC 64
#define NQ (BB * LL)
#define NVH 8
#define VH (VV / NVH)        // 1024 verts per CTA
#define NCH (VH / 64)        // 16 chunks of 64 verts
#define RX 136

static __device__ float    g_part[(size_t)NVH * NQ * RX];   // [vh][q][136]
static __device__ float4   g_vn[2 * BB * VV];                // (-2x,-2y,-2z,|v|^2), slot64-permuted
static __device__ uint16_t g_fhT[(size_t)2 * BB * CC * VV];  // fp16 feats^T, [bs][c][vslot]
static __device__ float    g_w1t[132 * 132];
static __device__ float    g_b1p[132];
static __device__ float    g_w2p[132];

// slot permutation within each 64-vert chunk:
// inv16 fragment order within k16, kk-pairs interleaved for LDS.128 B loads.
__host__ __device__ __forceinline__ int slot64(int k) {
    int kk = k >> 4, r = k & 15;
    int i = ((r >> 1) & 3) * 4 + (r & 1) + ((r >> 3) << 1);
    return (kk >> 1) * 32 + (i >> 2) * 8 + (kk & 1) * 4 + (i & 3);
}

__device__ __forceinline__ void cp16(uint32_t d, const void* s) {
    asm volatile("cp.async.cg.shared.global [%0], [%1], 16;" :: "r"(d), "l"(s));
}
__device__ __forceinline__ uint4 lds128(uint32_t addr) {
    uint4 r;
    asm volatile("ld.shared.v4.b32 {%0,%1,%2,%3}, [%4];"
                 : "=r"(r.x), "=r"(r.y), "=r"(r.z), "=r"(r.w) : "r"(addr));
    return r;
}
__device__ __forceinline__ uint32_t packh2(float lo, float hi) {
    uint32_t r;
    asm("cvt.rn.f16x2.f32 %0, %1, %2;" : "=r"(r) : "f"(hi), "f"(lo));
    return r;
}
__device__ __forceinline__ uint32_t ex2h2(uint32_t a) {
    uint32_t r;
    asm("ex2.approx.f16x2 %0, %1;" : "=r"(r) : "r"(a));
    return r;
}
// w pair from two fp32 squared distances: clamp->rsqrt->d->*(-log2e/sigma)->2^x
__device__ __forceinline__ uint32_t wpair(float d2a, float d2b) {
    const __half2 minn = __halves2half2(__ushort_as_half(0x0400), __ushort_as_half(0x0400));
    const __half2 negc = __float2half2_rn(-0.57707801635558535f);
    uint32_t u = packh2(d2a, d2b);
    __half2 v = __hmax2(*(__half2*)&u, minn);
    __half2 r = h2rsqrt(v);
    __half2 d = __hmul2(v, r);
    __half2 a = __hmul2(d, negc);
    return ex2h2(*(uint32_t*)&a);
}
__device__ __forceinline__ void mma16816(float* d, uint32_t a0, uint32_t a1, uint32_t a2,
                                         uint32_t a3, uint32_t b0, uint32_t b1) {
    asm volatile(
        "mma.sync.aligned.m16n8k16.row.col.f32.f16.f16.f32 "
        "{%0,%1,%2,%3},{%4,%5,%6,%7},{%8,%9},{%0,%1,%2,%3};"
        : "+f"(d[0]), "+f"(d[1]), "+f"(d[2]), "+f"(d[3])
        : "r"(a0), "r"(a1), "r"(a2), "r"(a3), "r"(b0), "r"(b1));
}

// ---------------- preps ----------------
__global__ void prep_vn_kernel(const float* __restrict__ vL, const float* __restrict__ vR) {
    const int v = blockIdx.x * 256 + threadIdx.x;
    const int bs = blockIdx.y, b = bs >> 1, side = bs & 1;
    const float* vp = (side ? vR : vL) + ((size_t)b * VV + v) * 3;
    const float x = vp[0], y = vp[1], z = vp[2];
    const int vs = (v & ~63) | slot64(v & 63);
    g_vn[(size_t)bs * VV + vs] =
        make_float4(-2.f * x, -2.f * y, -2.f * z, fmaf(x, x, fmaf(y, y, z * z)));
}

__global__ void prep_feats_kernel(const float* __restrict__ fL, const float* __restrict__ fR) {
    __shared__ float tile[64][65];
    const int vt = blockIdx.x, bs = blockIdx.y, b = bs >> 1, side = bs & 1;
    const int tid = threadIdx.x;
    const float* src = (side ? fR : fL) + ((size_t)b * VV + (size_t)vt * 64) * CC;
#pragma unroll
    for (int i = 0; i < 16; i++) {
        int idx = tid + 256 * i;
        tile[idx >> 6][idx & 63] = src[idx];
    }
    __syncthreads();
#pragma unroll
    for (int i = 0; i < 16; i++) {
        int idx = tid + 256 * i;
        int c = idx >> 6, v = idx & 63;
        g_fhT[((size_t)bs * CC + c) * VV + (size_t)vt * 64 + slot64(v)] =
            __half_as_ushort(__float2half_rn(tile[v][c]));
    }
}

__global__ void prep_w1_kernel(const float* __restrict__ w1, const float* __restrict__ b1,
                               const float* __restrict__ w2) {
    const int idx = blockIdx.x * 256 + threadIdx.x;
    if (idx < 132 * 132) {
        const int k = idx / 132, j = idx % 132;
        g_w1t[idx] = (j < 130 && k < 130) ? w1[j * 130 + k] : 0.f;
    }
    if (blockIdx.x == 0 && idx < 132) {
        g_b1p[idx] = (idx < 130) ? b1[idx] : 0.f;
        g_w2p[idx] = (idx < 130) ? w2[idx] : 0.f;
    }
}

// ---------------- fused interp ----------------
// grid (LL/128, 16, NVH), block 128 (4 warps, each M=32 x N=65)
// stage: feats rows 0..63 @0 (8192B), ones row 64 @8192, zeros rows 65..71 @8320, vn @9216
#define STG 10240

__global__ void __launch_bounds__(128, 4)
interp_kernel(const float* __restrict__ locsL, const float* __restrict__ locsR) {
    __shared__ __align__(1024) char smem[2 * STG];
    const uint32_t sb = (uint32_t)__cvta_generic_to_shared(smem);
    const int tid = threadIdx.x, lane = tid & 31, warp = tid >> 5;
    const int lt = blockIdx.x, bs = blockIdx.y, vh = blockIdx.z;
    const int b = bs >> 1, side = bs & 1;
    const int voff = vh * VH;

#pragma unroll
    for (int i = tid; i < 64; i += 128)
        ((uint32_t*)(smem + (i >> 5) * STG + 8192))[i & 31] = 0x3C003C00u;
    for (int i = tid; i < 448; i += 128)
        ((uint32_t*)(smem + (i / 224) * STG + 8320))[i % 224] = 0u;

    const float* locs = (side ? locsR : locsL) + (size_t)b * LL * 3;
    float px[4], py[4], pz[4], n2[4];
    const int rbase = lt * 128 + warp * 32 + (lane >> 2);
#pragma unroll
    for (int ri = 0; ri < 4; ri++) {
        const float* p = locs + (size_t)(rbase + ri * 8) * 3;
        px[ri] = p[0]; py[ri] = p[1]; pz[ri] = p[2];
        n2[ri] = fmaf(px[ri], px[ri], fmaf(py[ri], py[ri], pz[ri] * pz[ri]));
    }
    const uint16_t* fhb = g_fhT + (size_t)bs * CC * VV + voff;
    const float4*   vnb = g_vn + (size_t)bs * VV + voff;

    float acc[2][9][4];
#pragma unroll
    for (int m = 0; m < 2; m++)
#pragma unroll
        for (int t = 0; t < 9; t++)
#pragma unroll
            for (int i = 0; i < 4; i++) acc[m][t][i] = 0.f;

    auto stage_cp = [&](int ch) {
        const uint32_t dst = sb + (uint32_t)(ch & 1) * STG;
#pragma unroll
        for (int i = 0; i < 4; i++) {
            int idx = tid + i * 128;
            int c = idx >> 3, u = idx & 7;
            cp16(dst + c * 128 + ((u * 16) ^ ((c & 7) * 16)),
                 fhb + (size_t)c * VV + ch * 64 + u * 8);
        }
        if (tid < 64) cp16(dst + 9216 + tid * 16, vnb + ch * 64 + tid);
        asm volatile("cp.async.commit_group;");
    };

    stage_cp(0);
    stage_cp(1);

    const uint32_t bswz = (uint32_t)((lane >> 2) << 4);
    const int q = lane & 3;

    for (int ch = 0; ch < NCH; ch++) {
        const int s = ch & 1;
        if (ch == NCH - 1) asm volatile("cp.async.wait_group 0;");
        else               asm volatile("cp.async.wait_group 1;");
        __syncthreads();

        const uint32_t fbase = sb + (uint32_t)s * STG;
        const float4* vns = (const float4*)(smem + (size_t)s * STG + 9216);

#pragma unroll 1
        for (int p = 0; p < 2; p++) {
            uint32_t HI[2][4][2];
#pragma unroll
            for (int h = 0; h < 2; h++) {
                float4 vq[4];
#pragma unroll
                for (int j = 0; j < 4; j++) vq[j] = vns[p * 32 + q * 8 + h * 4 + j];
#pragma unroll
                for (int ri = 0; ri < 4; ri++) {
                    float d2a[4];
#pragma unroll
                    for (int j = 0; j < 4; j++) {
                        float s0 = n2[ri] + vq[j].w;
                        d2a[j] = fmaf(px[ri], vq[j].x,
                                 fmaf(py[ri], vq[j].y,
                                 fmaf(pz[ri], vq[j].z, s0)));
                    }
                    HI[h][ri][0] = wpair(d2a[0], d2a[1]);
                    HI[h][ri][1] = wpair(d2a[2], d2a[3]);
                }
            }

            const uint32_t kb = (uint32_t)(p * 64 + q * 16) ^ bswz;
#pragma unroll
            for (int t = 0; t < 9; t++) {
                const uint32_t addr = fbase + (uint32_t)((t * 8 + (lane >> 2)) * 128) + kb;
                uint4 bb = lds128(addr);
                mma16816(acc[0][t], HI[0][0][0], HI[0][1][0], HI[0][0][1], HI[0][1][1], bb.x, bb.y);
                mma16816(acc[1][t], HI[0][2][0], HI[0][3][0], HI[0][2][1], HI[0][3][1], bb.x, bb.y);
                mma16816(acc[0][t], HI[1][0][0], HI[1][1][0], HI[1][0][1], HI[1][1][1], bb.z, bb.w);
                mma16816(acc[1][t], HI[1][2][0], HI[1][3][0], HI[1][2][1], HI[1][3][1], bb.z, bb.w);
            }
        }
        __syncthreads();
        if (ch + 2 < NCH) stage_cp(ch + 2);
    }

    // unnormalized partials + dens (dens = D column 64, lane&3==0)
#pragma unroll
    for (int ri = 0; ri < 4; ri++) {
        const size_t qq = (size_t)b * LL + rbase + ri * 8;
        float* orow = g_part + ((size_t)vh * NQ + qq) * RX + side * 68;
        const int mt = ri >> 1, rp = (ri & 1) * 2;
#pragma unroll
        for (int t = 0; t < 8; t++) {
            float2 v2;
            v2.x = acc[mt][t][rp + 0];
            v2.y = acc[mt][t][rp + 1];
            *(float2*)(orow + t * 8 + q * 2) = v2;
        }
        if (q == 0) orow[64] = acc[mt][8][rp];
    }
}

// ---------------- MLP ----------------
__global__ void __launch_bounds__(256) mlp_kernel(const float* __restrict__ b2,
                                                  float* __restrict__ out) {
    __shared__ float xs[8][4][132];
    const int warp = threadIdx.x >> 5;
    const int lane = threadIdx.x & 31;
    const int q0 = (blockIdx.x * 8 + warp) * 4;

#pragma unroll
    for (int qq = 0; qq < 4; qq++) {
        const size_t q = q0 + qq;
        float v[5];
#pragma unroll
        for (int m = 0; m < 5; m++) {
            const int c = lane + 32 * m;
            float sum = 0.f;
            if (c < 130) {
                const int pc = c < 65 ? c : c + 3;
#pragma unroll
                for (int s = 0; s < NVH; s++)
                    sum += g_part[((size_t)s * NQ + q) * RX + pc];
            }
            v[m] = sum;
        }
        const float dl = __shfl_sync(0xFFFFFFFFu, v[2], 0);
        const float dr = __shfl_sync(0xFFFFFFFFu, v[4], 1);
        const float il = 1.f / dl, ir = 1.f / dr;
#pragma unroll
        for (int m = 0; m < 5; m++) {
            const int c = lane + 32 * m;
            if (c < 64)        xs[warp][qq][c] = v[m] * il;
            else if (c == 64)  xs[warp][qq][64] = dl;
            else if (c < 129)  xs[warp][qq][c] = v[m] * ir;
            else if (c == 129) xs[warp][qq][129] = dr;
        }
    }
    __syncwarp();

    const float4* wv = (const float4*)g_w1t;
    float4 hA[4], hB[4];
#pragma unroll
    for (int qq = 0; qq < 4; qq++) { hA[qq] = make_float4(0, 0, 0, 0); hB[qq] = hA[qq]; }
#pragma unroll 2
    for (int k = 0; k < 130; k++) {
        const float4 wA = wv[k * 33 + lane];
        const float4 wB = wv[k * 33 + 32];
#pragma unroll
        for (int qq = 0; qq < 4; qq++) {
            const float x = xs[warp][qq][k];
            hA[qq].x = fmaf(wA.x, x, hA[qq].x); hA[qq].y = fmaf(wA.y, x, hA[qq].y);
            hA[qq].z = fmaf(wA.z, x, hA[qq].z); hA[qq].w = fmaf(wA.w, x, hA[qq].w);
            hB[qq].x = fmaf(wB.x, x, hB[qq].x); hB[qq].y = fmaf(wB.y, x, hB[qq].y);
            hB[qq].z = fmaf(wB.z, x, hB[qq].z); hB[qq].w = fmaf(wB.w, x, hB[qq].w);
        }
    }
    const float4 b1A = ((const float4*)g_b1p)[lane];
    const float4 w2A = ((const float4*)g_w2p)[lane];
    const float4 b1B = ((const float4*)g_b1p)[32];
    const float4 w2B = ((const float4*)g_w2p)[32];
    const float bb = b2[0];

#pragma unroll
    for (int qq = 0; qq < 4; qq++) {
        float r = fmaxf(hA[qq].x + b1A.x, 0.f) * w2A.x + fmaxf(hA[qq].y + b1A.y, 0.f) * w2A.y
                + fmaxf(hA[qq].z + b1A.z, 0.f) * w2A.z + fmaxf(hA[qq].w + b1A.w, 0.f) * w2A.w;
        if (lane == 0)
            r += fmaxf(hB[qq].x + b1B.x, 0.f) * w2B.x + fmaxf(hB[qq].y + b1B.y, 0.f) * w2B.y
               + fmaxf(hB[qq].z + b1B.z, 0.f) * w2B.z + fmaxf(hB[qq].w + b1B.w, 0.f) * w2B.w;
#pragma unroll
        for (int o = 16; o > 0; o >>= 1) r += __shfl_xor_sync(0xFFFFFFFFu, r, o);
        if (lane == 0) out[q0 + qq] = r + bb;
    }
}

extern "C" void kernel_launch(void* const* d_in, const int* in_sizes, int n_in,
                              void* d_out, int out_size) {
    (void)in_sizes; (void)n_in; (void)out_size;
    const float* locsL  = (const float*)d_in[0];
    const float* locsR  = (const float*)d_in[1];
    const float* vertsL = (const float*)d_in[2];
    const float* vertsR = (const float*)d_in[3];
    const float* featsL = (const float*)d_in[4];
    const float* featsR = (const float*)d_in[5];
    const float* w1     = (const float*)d_in[6];
    const float* b1     = (const float*)d_in[7];
    const float* w2     = (const float*)d_in[8];
    const float* b2     = (const float*)d_in[9];
    float* out = (float*)d_out;

    prep_vn_kernel<<<dim3(VV / 256, 16), 256>>>(vertsL, vertsR);
    prep_feats_kernel<<<dim3(VV / 64, 16), 256>>>(featsL, featsR);
    prep_w1_kernel<<<69, 256>>>(w1, b1, w2);
    interp_kernel<<<dim3(LL / 128, 16, NVH), 128>>>(locsL, locsR);
    mlp_kernel<<<NQ / 32, 256>>>(b2, out);
}

// round 10
// speedup vs baseline: 1.2144x; 1.2144x over previous
#include <cuda_runtime.h>
#include <cuda_fp16.h>
#include <cstdint>

#define BB 8
#define LL 2048
#define VV 8192
#define CC 64
#define NQ (BB * LL)
#define NVH 8
#define VH (VV / NVH)        // 1024 verts per CTA
#define NCH (VH / 64)        // 16 chunks of 64 verts
#define NCG (VV / 64)        // 128 chunks globally
#define RX 136

static __device__ float  g_part[(size_t)NVH * NQ * RX];     // [vh][q][136]
static __device__ float4 g_vn[2 * BB * VV];                  // (-2x,-2y,-2z,|v|^2), natural order
static __device__ uint2  g_fB[(size_t)2 * BB * NCG * 1024];  // frag-major fp16 B tiles
static __device__ float  g_w1t[132 * 132];
static __device__ float  g_b1p[132];
static __device__ float  g_w2p[132];

__device__ __forceinline__ void cp16(uint32_t d, const void* s) {
    asm volatile("cp.async.cg.shared.global [%0], [%1], 16;" :: "r"(d), "l"(s));
}
__device__ __forceinline__ void lds64(uint32_t& a, uint32_t& b, uint32_t addr) {
    asm volatile("ld.shared.v2.b32 {%0,%1}, [%2];" : "=r"(a), "=r"(b) : "r"(addr));
}
__device__ __forceinline__ uint32_t packh2(float lo, float hi) {
    uint32_t r;
    asm("cvt.rn.f16x2.f32 %0, %1, %2;" : "=r"(r) : "f"(hi), "f"(lo));
    return r;
}
__device__ __forceinline__ uint32_t ex2h2(uint32_t a) {
    uint32_t r;
    asm("ex2.approx.f16x2 %0, %1;" : "=r"(r) : "r"(a));
    return r;
}
// w pair from two fp32 squared distances: clamp->rsqrt->d->*(-log2e/sigma)->2^x
__device__ __forceinline__ uint32_t wpair(float d2a, float d2b) {
    const __half2 minn = __halves2half2(__ushort_as_half(0x0400), __ushort_as_half(0x0400));
    const __half2 negc = __float2half2_rn(-0.57707801635558535f);
    uint32_t u = packh2(d2a, d2b);
    __half2 v = __hmax2(*(__half2*)&u, minn);
    __half2 r = h2rsqrt(v);
    __half2 d = __hmul2(v, r);
    __half2 a = __hmul2(d, negc);
    return ex2h2(*(uint32_t*)&a);
}
__device__ __forceinline__ void mma16816(float* d, uint32_t a0, uint32_t a1, uint32_t a2,
                                         uint32_t a3, uint32_t b0, uint32_t b1) {
    asm volatile(
        "mma.sync.aligned.m16n8k16.row.col.f32.f16.f16.f32 "
        "{%0,%1,%2,%3},{%4,%5,%6,%7},{%8,%9},{%0,%1,%2,%3};"
        : "+f"(d[0]), "+f"(d[1]), "+f"(d[2]), "+f"(d[3])
        : "r"(a0), "r"(a1), "r"(a2), "r"(a3), "r"(b0), "r"(b1));
}

// ---------------- preps ----------------
__global__ void prep_vn_kernel(const float* __restrict__ vL, const float* __restrict__ vR) {
    const int v = blockIdx.x * 256 + threadIdx.x;
    const int bs = blockIdx.y, b = bs >> 1, side = bs & 1;
    const float* vp = (side ? vR : vL) + ((size_t)b * VV + v) * 3;
    const float x = vp[0], y = vp[1], z = vp[2];
    g_vn[(size_t)bs * VV + v] =
        make_float4(-2.f * x, -2.f * y, -2.f * z, fmaf(x, x, fmaf(y, y, z * z)));
}

// fragment-major B: per (bs, chunk ci): frag[kk][t][lane] uint2,
//   c = t*8 + (lane>>2);  v = ci*64 + kk*16 + (lane&3)*4 + {0..3}
//   .x = pack(f[v0][c], f[v1][c]),  .y = pack(f[v2][c], f[v3][c])
__global__ void prep_feats_kernel(const float* __restrict__ fL, const float* __restrict__ fR) {
    __shared__ float tile[64][65];
    const int ci = blockIdx.x, bs = blockIdx.y, b = bs >> 1, side = bs & 1;
    const int tid = threadIdx.x;
    const float* src = (side ? fR : fL) + ((size_t)b * VV + (size_t)ci * 64) * CC;
#pragma unroll
    for (int i = 0; i < 16; i++) {
        int idx = tid + 256 * i;
        tile[idx >> 6][idx & 63] = src[idx];   // tile[v][c]
    }
    __syncthreads();
    uint2* dst = g_fB + ((size_t)bs * NCG + ci) * 1024;
#pragma unroll
    for (int i = 0; i < 4; i++) {
        int idx = tid + 256 * i;               // 0..1023 = (kk*8+t)*32+lane
        int lane = idx & 31, t = (idx >> 5) & 7, kk = idx >> 8;
        int c = t * 8 + (lane >> 2);
        int v0 = kk * 16 + (lane & 3) * 4;
        __half2 p0 = __floats2half2_rn(tile[v0 + 0][c], tile[v0 + 1][c]);
        __half2 p1 = __floats2half2_rn(tile[v0 + 2][c], tile[v0 + 3][c]);
        uint2 o; o.x = *(uint32_t*)&p0; o.y = *(uint32_t*)&p1;
        dst[idx] = o;
    }
}

__global__ void prep_w1_kernel(const float* __restrict__ w1, const float* __restrict__ b1,
                               const float* __restrict__ w2) {
    const int idx = blockIdx.x * 256 + threadIdx.x;
    if (idx < 132 * 132) {
        const int k = idx / 132, j = idx % 132;
        g_w1t[idx] = (j < 130 && k < 130) ? w1[j * 130 + k] : 0.f;
    }
    if (blockIdx.x == 0 && idx < 132) {
        g_b1p[idx] = (idx < 130) ? b1[idx] : 0.f;
        g_w2p[idx] = (idx < 130) ? w2[idx] : 0.f;
    }
}

// ---------------- fused interp ----------------
// grid (LL/128, 16, NVH), block 128 (4 warps, each M=32 x N=65)
// stage: B frags @0 (8192B), vn @8192 (1024B)
#define STG 9216

__global__ void __launch_bounds__(128, 4)
interp_kernel(const float* __restrict__ locsL, const float* __restrict__ locsR) {
    __shared__ __align__(1024) char smem[2 * STG];
    const uint32_t sb = (uint32_t)__cvta_generic_to_shared(smem);
    const int tid = threadIdx.x, lane = tid & 31, warp = tid >> 5;
    const int lt = blockIdx.x, bs = blockIdx.y, vh = blockIdx.z;
    const int b = bs >> 1, side = bs & 1;

    const float* locs = (side ? locsR : locsL) + (size_t)b * LL * 3;
    float px[4], py[4], pz[4], n2[4];
    const int rbase = lt * 128 + warp * 32 + (lane >> 2);
#pragma unroll
    for (int ri = 0; ri < 4; ri++) {
        const float* p = locs + (size_t)(rbase + ri * 8) * 3;
        px[ri] = p[0]; py[ri] = p[1]; pz[ri] = p[2];
        n2[ri] = fmaf(px[ri], px[ri], fmaf(py[ri], py[ri], pz[ri] * pz[ri]));
    }
    const uint2*  fbb = g_fB + ((size_t)bs * NCG + vh * NCH) * 1024;
    const float4* vnb = g_vn + (size_t)bs * VV + vh * VH;

    // t=8 constant B fragment (dens column: channel 64 = ones, 65..71 zero)
    const uint32_t bcst = ((lane >> 2) == 0) ? 0x3C003C00u : 0u;

    float acc[2][9][4];
#pragma unroll
    for (int m = 0; m < 2; m++)
#pragma unroll
        for (int t = 0; t < 9; t++)
#pragma unroll
            for (int i = 0; i < 4; i++) acc[m][t][i] = 0.f;

    auto stage_cp = [&](int ch) {
        const uint32_t dst = sb + (uint32_t)(ch & 1) * STG;
        const char* src = (const char*)(fbb + (size_t)ch * 1024);
#pragma unroll
        for (int i = 0; i < 4; i++)
            cp16(dst + (tid + i * 128) * 16, src + (tid + i * 128) * 16);
        if (tid < 64) cp16(dst + 8192 + tid * 16, vnb + ch * 64 + tid);
        asm volatile("cp.async.commit_group;");
    };

    stage_cp(0);
    stage_cp(1);

    const int q = lane & 3;

    for (int ch = 0; ch < NCH; ch++) {
        const int s = ch & 1;
        if (ch == NCH - 1) asm volatile("cp.async.wait_group 0;");
        else               asm volatile("cp.async.wait_group 1;");
        __syncthreads();

        const uint32_t lb = sb + (uint32_t)s * STG + (uint32_t)lane * 8;
        const float4* vns = (const float4*)(smem + (size_t)s * STG + 8192);

#pragma unroll 1
        for (int kk = 0; kk < 4; kk++) {
            float4 vq[4];
#pragma unroll
            for (int j = 0; j < 4; j++) vq[j] = vns[kk * 16 + q * 4 + j];

            uint32_t HI[4][2];
#pragma unroll
            for (int ri = 0; ri < 4; ri++) {
                float d2a[4];
#pragma unroll
                for (int j = 0; j < 4; j++) {
                    float s0 = n2[ri] + vq[j].w;
                    d2a[j] = fmaf(px[ri], vq[j].x,
                             fmaf(py[ri], vq[j].y,
                             fmaf(pz[ri], vq[j].z, s0)));
                }
                HI[ri][0] = wpair(d2a[0], d2a[1]);
                HI[ri][1] = wpair(d2a[2], d2a[3]);
            }

#pragma unroll
            for (int t = 0; t < 8; t++) {
                uint32_t bh0, bh1;
                lds64(bh0, bh1, lb + (uint32_t)((kk * 8 + t) * 256));
                mma16816(acc[0][t], HI[0][0], HI[1][0], HI[0][1], HI[1][1], bh0, bh1);
                mma16816(acc[1][t], HI[2][0], HI[3][0], HI[2][1], HI[3][1], bh0, bh1);
            }
            mma16816(acc[0][8], HI[0][0], HI[1][0], HI[0][1], HI[1][1], bcst, bcst);
            mma16816(acc[1][8], HI[2][0], HI[3][0], HI[2][1], HI[3][1], bcst, bcst);
        }
        __syncthreads();
        if (ch + 2 < NCH) stage_cp(ch + 2);
    }

    // unnormalized partials + dens (dens = D column 64, lane&3==0)
#pragma unroll
    for (int ri = 0; ri < 4; ri++) {
        const size_t qq = (size_t)b * LL + rbase + ri * 8;
        float* orow = g_part + ((size_t)vh * NQ + qq) * RX + side * 68;
        const int mt = ri >> 1, rp = (ri & 1) * 2;
#pragma unroll
        for (int t = 0; t < 8; t++) {
            float2 v2;
            v2.x = acc[mt][t][rp + 0];
            v2.y = acc[mt][t][rp + 1];
            *(float2*)(orow + t * 8 + q * 2) = v2;
        }
        if (q == 0) orow[64] = acc[mt][8][rp];
    }
}

// ---------------- MLP ----------------
__global__ void __launch_bounds__(256) mlp_kernel(const float* __restrict__ b2,
                                                  float* __restrict__ out) {
    __shared__ float xs[8][4][132];
    const int warp = threadIdx.x >> 5;
    const int lane = threadIdx.x & 31;
    const int q0 = (blockIdx.x * 8 + warp) * 4;

#pragma unroll
    for (int qq = 0; qq < 4; qq++) {
        const size_t q = q0 + qq;
        float v[5];
#pragma unroll
        for (int m = 0; m < 5; m++) {
            const int c = lane + 32 * m;
            float sum = 0.f;
            if (c < 130) {
                const int pc = c < 65 ? c : c + 3;
#pragma unroll
                for (int s = 0; s < NVH; s++)
                    sum += g_part[((size_t)s * NQ + q) * RX + pc];
            }
            v[m] = sum;
        }
        const float dl = __shfl_sync(0xFFFFFFFFu, v[2], 0);
        const float dr = __shfl_sync(0xFFFFFFFFu, v[4], 1);
        const float il = 1.f / dl, ir = 1.f / dr;
#pragma unroll
        for (int m = 0; m < 5; m++) {
            const int c = lane + 32 * m;
            if (c < 64)        xs[warp][qq][c] = v[m] * il;
            else if (c == 64)  xs[warp][qq][64] = dl;
            else if (c < 129)  xs[warp][qq][c] = v[m] * ir;
            else if (c == 129) xs[warp][qq][129] = dr;
        }
    }
    __syncwarp();

    const float4* wv = (const float4*)g_w1t;
    float4 hA[4], hB[4];
#pragma unroll
    for (int qq = 0; qq < 4; qq++) { hA[qq] = make_float4(0, 0, 0, 0); hB[qq] = hA[qq]; }
#pragma unroll 2
    for (int k = 0; k < 130; k++) {
        const float4 wA = wv[k * 33 + lane];
        const float4 wB = wv[k * 33 + 32];
#pragma unroll
        for (int qq = 0; qq < 4; qq++) {
            const float x = xs[warp][qq][k];
            hA[qq].x = fmaf(wA.x, x, hA[qq].x); hA[qq].y = fmaf(wA.y, x, hA[qq].y);
            hA[qq].z = fmaf(wA.z, x, hA[qq].z); hA[qq].w = fmaf(wA.w, x, hA[qq].w);
            hB[qq].x = fmaf(wB.x, x, hB[qq].x); hB[qq].y = fmaf(wB.y, x, hB[qq].y);
            hB[qq].z = fmaf(wB.z, x, hB[qq].z); hB[qq].w = fmaf(wB.w, x, hB[qq].w);
        }
    }
    const float4 b1A = ((const float4*)g_b1p)[lane];
    const float4 w2A = ((const float4*)g_w2p)[lane];
    const float4 b1B = ((const float4*)g_b1p)[32];
    const float4 w2B = ((const float4*)g_w2p)[32];
    const float bb = b2[0];

#pragma unroll
    for (int qq = 0; qq < 4; qq++) {
        float r = fmaxf(hA[qq].x + b1A.x, 0.f) * w2A.x + fmaxf(hA[qq].y + b1A.y, 0.f) * w2A.y
                + fmaxf(hA[qq].z + b1A.z, 0.f) * w2A.z + fmaxf(hA[qq].w + b1A.w, 0.f) * w2A.w;
        if (lane == 0)
            r += fmaxf(hB[qq].x + b1B.x, 0.f) * w2B.x + fmaxf(hB[qq].y + b1B.y, 0.f) * w2B.y
               + fmaxf(hB[qq].z + b1B.z, 0.f) * w2B.z + fmaxf(hB[qq].w + b1B.w, 0.f) * w2B.w;
#pragma unroll
        for (int o = 16; o > 0; o >>= 1) r += __shfl_xor_sync(0xFFFFFFFFu, r, o);
        if (lane == 0) out[q0 + qq] = r + bb;
    }
}

extern "C" void kernel_launch(void* const* d_in, const int* in_sizes, int n_in,
                              void* d_out, int out_size) {
    (void)in_sizes; (void)n_in; (void)out_size;
    const float* locsL  = (const float*)d_in[0];
    const float* locsR  = (const float*)d_in[1];
    const float* vertsL = (const float*)d_in[2];
    const float* vertsR = (const float*)d_in[3];
    const float* featsL = (const float*)d_in[4];
    const float* featsR = (const float*)d_in[5];
    const float* w1     = (const float*)d_in[6];
    const float* b1     = (const float*)d_in[7];
    const float* w2     = (const float*)d_in[8];
    const float* b2     = (const float*)d_in[9];
    float* out = (float*)d_out;

    prep_vn_kernel<<<dim3(VV / 256, 16), 256>>>(vertsL, vertsR);
    prep_feats_kernel<<<dim3(NCG, 16), 256>>>(featsL, featsR);
    prep_w1_kernel<<<69, 256>>>(w1, b1, w2);
    interp_kernel<<<dim3(LL / 128, 16, NVH), 128>>>(locsL, locsR);
    mlp_kernel<<<NQ / 32, 256>>>(b2, out);
}